// round 5
// baseline (speedup 1.0000x reference)
#include <cuda_runtime.h>
#include <cstdint>
#include <cstddef>

// Problem constants
#define B_   4
#define C_   384
#define S_   4096
#define OC3_ 1152   // 3*C_

// ---------------------------------------------------------------------------
// Scratch (device globals; no allocation allowed in kernel_launch)
// ---------------------------------------------------------------------------
__device__ float g_scl[B_ * S_];                       // per-pixel rms scale
__device__ float g_wg [OC3_ * C_];                     // w_qkv * gamma
__device__ float g_qkv[(size_t)B_ * OC3_ * S_];        // [b][o][s]
__device__ float g_P  [(size_t)B_ * S_ * S_];          // [b][i][j] scores/attn
__device__ float g_O  [(size_t)B_ * C_ * S_];          // [b][c][s] attn output

// ---------------------------------------------------------------------------
// Prep kernels
// ---------------------------------------------------------------------------
__global__ void wg_kernel(float* __restrict__ wg, const float* __restrict__ w,
                          const float* __restrict__ g) {
    int i = blockIdx.x * 256 + threadIdx.x;
    if (i < OC3_ * C_) wg[i] = w[i] * g[i % C_];
}

__global__ void scale_kernel(float* __restrict__ scl, const float* __restrict__ x) {
    int s = blockIdx.x * 256 + threadIdx.x;
    int b = blockIdx.y;
    const float* xb = x + (size_t)b * C_ * S_ + s;
    float acc = 0.f;
#pragma unroll 8
    for (int c = 0; c < C_; ++c) {
        float v = xb[(size_t)c * S_];
        acc += v * v;
    }
    float l2 = sqrtf(acc);
    // xn = x / max(l2, eps) * sqrt(C)
    scl[b * S_ + s] = 19.595917942265423f / fmaxf(l2, 1e-12f);
}

// ---------------------------------------------------------------------------
// Generic 128x128x16 SGEMM with f32x2 packed FMA inner loop.
//   AL: 0 = A[k*lda + m] (K-strided, M contiguous), 1 = A[m*lda + k]
//   BL: 0 = B[k*ldb + n],                           1 = B[n*ldb + k]
//   EPI: 0 qkv (acc*e1[n] + e2[m]) | 1 scores (acc/sqrt(C)) | 2 plain
//        3 proj (acc + e2[m] + e3[m*ldc+n])
// All dims are exact multiples of tile sizes for this problem (no bounds checks).
// ---------------------------------------------------------------------------
template <int AL, int BL, int EPI>
__global__ __launch_bounds__(256, 2)
void gemm_kernel(const float* __restrict__ Ag, const float* __restrict__ Bg,
                 float* __restrict__ Cg,
                 int K, int lda, int ldb, int ldc,
                 size_t sA, size_t sB, size_t sC,
                 const float* __restrict__ e1, const float* __restrict__ e2,
                 const float* __restrict__ e3,
                 size_t e1s, size_t e3s)
{
    __shared__ __align__(16) float As[16][132];
    __shared__ __align__(16) float Bs[16][132];

    const int tid = threadIdx.x;
    const int tx = tid & 15;          // n group
    const int ty = tid >> 4;          // m group
    const int b  = blockIdx.z;
    const int mBlk = blockIdx.y * 128;
    const int nBlk = blockIdx.x * 128;

    const float* A  = Ag + (size_t)b * sA;
    const float* Bp = Bg + (size_t)b * sB;
    float*       Cp = Cg + (size_t)b * sC;
    const float* e1p = (EPI == 0) ? (e1 + (size_t)b * e1s) : nullptr;
    const float* e3p = (EPI == 3) ? (e3 + (size_t)b * e3s) : nullptr;

    // acc[n][mp]: mp packs two consecutive m values into one f32x2 register pair
    unsigned long long acc[8][4];
#pragma unroll
    for (int n = 0; n < 8; ++n)
#pragma unroll
        for (int mp = 0; mp < 4; ++mp) acc[n][mp] = 0ull;

    const uint32_t asBase = (uint32_t)__cvta_generic_to_shared(&As[0][0]);

    for (int k0 = 0; k0 < K; k0 += 16) {
        // ---- load A tile into As[k][m] ----
        if (AL == 0) {
#pragma unroll
            for (int it = 0; it < 2; ++it) {
                int kk = (tid >> 5) + it * 8;
                int m4 = (tid & 31) * 4;
                float4 v = *reinterpret_cast<const float4*>(
                    A + (size_t)(k0 + kk) * lda + mBlk + m4);
                *reinterpret_cast<float4*>(&As[kk][m4]) = v;
            }
        } else {
#pragma unroll
            for (int it = 0; it < 2; ++it) {
                int idx = it * 256 + tid;
                int r = idx >> 2, q = idx & 3;
                float4 v = *reinterpret_cast<const float4*>(
                    A + (size_t)(mBlk + r) * lda + k0 + q * 4);
                As[q * 4 + 0][r] = v.x;
                As[q * 4 + 1][r] = v.y;
                As[q * 4 + 2][r] = v.z;
                As[q * 4 + 3][r] = v.w;
            }
        }
        // ---- load B tile into Bs[k][n] ----
        if (BL == 0) {
#pragma unroll
            for (int it = 0; it < 2; ++it) {
                int kk = (tid >> 5) + it * 8;
                int n4 = (tid & 31) * 4;
                float4 v = *reinterpret_cast<const float4*>(
                    Bp + (size_t)(k0 + kk) * ldb + nBlk + n4);
                *reinterpret_cast<float4*>(&Bs[kk][n4]) = v;
            }
        } else {
#pragma unroll
            for (int it = 0; it < 2; ++it) {
                int idx = it * 256 + tid;
                int r = idx >> 2, q = idx & 3;
                float4 v = *reinterpret_cast<const float4*>(
                    Bp + (size_t)(nBlk + r) * ldb + k0 + q * 4);
                Bs[q * 4 + 0][r] = v.x;
                Bs[q * 4 + 1][r] = v.y;
                Bs[q * 4 + 2][r] = v.z;
                Bs[q * 4 + 3][r] = v.w;
            }
        }
        __syncthreads();

        // ---- inner product: 32 f32x2 FMAs per k-step ----
#pragma unroll
        for (int kk = 0; kk < 16; ++kk) {
            unsigned long long a2[4];
            uint32_t aAddr = asBase + (uint32_t)kk * 528u + (uint32_t)ty * 16u;
            asm volatile("ld.shared.v2.b64 {%0,%1}, [%2];"
                         : "=l"(a2[0]), "=l"(a2[1]) : "r"(aAddr));
            asm volatile("ld.shared.v2.b64 {%0,%1}, [%2];"
                         : "=l"(a2[2]), "=l"(a2[3]) : "r"(aAddr + 256u));

            float4 b0 = *reinterpret_cast<const float4*>(&Bs[kk][tx * 4]);
            float4 b1 = *reinterpret_cast<const float4*>(&Bs[kk][64 + tx * 4]);

            unsigned long long bd[8];
            asm("mov.b64 %0, {%1,%1};" : "=l"(bd[0]) : "f"(b0.x));
            asm("mov.b64 %0, {%1,%1};" : "=l"(bd[1]) : "f"(b0.y));
            asm("mov.b64 %0, {%1,%1};" : "=l"(bd[2]) : "f"(b0.z));
            asm("mov.b64 %0, {%1,%1};" : "=l"(bd[3]) : "f"(b0.w));
            asm("mov.b64 %0, {%1,%1};" : "=l"(bd[4]) : "f"(b1.x));
            asm("mov.b64 %0, {%1,%1};" : "=l"(bd[5]) : "f"(b1.y));
            asm("mov.b64 %0, {%1,%1};" : "=l"(bd[6]) : "f"(b1.z));
            asm("mov.b64 %0, {%1,%1};" : "=l"(bd[7]) : "f"(b1.w));

#pragma unroll
            for (int n = 0; n < 8; ++n)
#pragma unroll
                for (int mp = 0; mp < 4; ++mp)
                    asm("fma.rn.f32x2 %0, %1, %2, %0;"
                        : "+l"(acc[n][mp]) : "l"(a2[mp]), "l"(bd[n]));
        }
        __syncthreads();
    }

    // ---- epilogue ----
#pragma unroll
    for (int n = 0; n < 8; ++n) {
        int gn = nBlk + ((n < 4) ? (tx * 4 + n) : (64 + tx * 4 + n - 4));
        float colScale = 1.f;
        if (EPI == 0) colScale = e1p[gn];
#pragma unroll
        for (int mp = 0; mp < 4; ++mp) {
            float lo, hi;
            asm("mov.b64 {%0,%1}, %2;" : "=f"(lo), "=f"(hi) : "l"(acc[n][mp]));
            int gm = mBlk + ((mp < 2) ? 0 : 64) + ty * 4 + (mp & 1) * 2;
            float vlo, vhi;
            if (EPI == 0) {
                vlo = lo * colScale + e2[gm];
                vhi = hi * colScale + e2[gm + 1];
            } else if (EPI == 1) {
                vlo = lo * 0.05103103630798288f;   // 1/sqrt(384)
                vhi = hi * 0.05103103630798288f;
            } else if (EPI == 2) {
                vlo = lo; vhi = hi;
            } else { // EPI == 3
                vlo = lo + e2[gm]     + e3p[(size_t)gm       * ldc + gn];
                vhi = hi + e2[gm + 1] + e3p[(size_t)(gm + 1) * ldc + gn];
            }
            Cp[(size_t)gm       * ldc + gn] = vlo;
            Cp[(size_t)(gm + 1) * ldc + gn] = vhi;
        }
    }
}

// ---------------------------------------------------------------------------
// Row softmax over 4096 columns, one block per row, data kept in registers.
// ---------------------------------------------------------------------------
__global__ void softmax_kernel(float* __restrict__ P) {
    float4* p = reinterpret_cast<float4*>(P + (size_t)blockIdx.x * S_);
    const int t = threadIdx.x;

    float4 v[4];
    float mx = -3.4e38f;
#pragma unroll
    for (int i = 0; i < 4; ++i) {
        v[i] = p[t + i * 256];
        mx = fmaxf(mx, fmaxf(fmaxf(v[i].x, v[i].y), fmaxf(v[i].z, v[i].w)));
    }
    __shared__ float redMax[8];
    __shared__ float redSum[8];
#pragma unroll
    for (int o = 16; o > 0; o >>= 1)
        mx = fmaxf(mx, __shfl_xor_sync(0xffffffffu, mx, o));
    if ((t & 31) == 0) redMax[t >> 5] = mx;
    __syncthreads();
    mx = redMax[0];
#pragma unroll
    for (int w = 1; w < 8; ++w) mx = fmaxf(mx, redMax[w]);

    float sum = 0.f;
#pragma unroll
    for (int i = 0; i < 4; ++i) {
        v[i].x = __expf(v[i].x - mx);
        v[i].y = __expf(v[i].y - mx);
        v[i].z = __expf(v[i].z - mx);
        v[i].w = __expf(v[i].w - mx);
        sum += (v[i].x + v[i].y) + (v[i].z + v[i].w);
    }
#pragma unroll
    for (int o = 16; o > 0; o >>= 1)
        sum += __shfl_xor_sync(0xffffffffu, sum, o);
    if ((t & 31) == 0) redSum[t >> 5] = sum;
    __syncthreads();
    sum = (redSum[0] + redSum[1]) + (redSum[2] + redSum[3]) +
          (redSum[4] + redSum[5]) + (redSum[6] + redSum[7]);
    float inv = 1.f / sum;
#pragma unroll
    for (int i = 0; i < 4; ++i) {
        v[i].x *= inv; v[i].y *= inv; v[i].z *= inv; v[i].w *= inv;
        p[t + i * 256] = v[i];
    }
}

// ---------------------------------------------------------------------------
// Launch
// ---------------------------------------------------------------------------
extern "C" void kernel_launch(void* const* d_in, const int* in_sizes, int n_in,
                              void* d_out, int out_size) {
    const float* x      = (const float*)d_in[0];   // [4,384,64,64]
    const float* gamma  = (const float*)d_in[1];   // [384]
    const float* w_qkv  = (const float*)d_in[2];   // [1152,384]
    const float* b_qkv  = (const float*)d_in[3];   // [1152]
    const float* w_proj = (const float*)d_in[4];   // [384,384]
    const float* b_proj = (const float*)d_in[5];   // [384]
    float* out = (float*)d_out;                    // [4,384,64,64]

    float *scl, *wg, *qkv, *P, *O;
    cudaGetSymbolAddress((void**)&scl, g_scl);
    cudaGetSymbolAddress((void**)&wg,  g_wg);
    cudaGetSymbolAddress((void**)&qkv, g_qkv);
    cudaGetSymbolAddress((void**)&P,   g_P);
    cudaGetSymbolAddress((void**)&O,   g_O);

    // 1) fold gamma into w_qkv
    wg_kernel<<<(OC3_ * C_ + 255) / 256, 256>>>(wg, w_qkv, gamma);
    // 2) per-pixel rms scale
    scale_kernel<<<dim3(S_ / 256, B_), 256>>>(scl, x);
    // 3) qkv = (Wg @ x) * scl[s] + b_qkv   -> [b,1152,s]
    gemm_kernel<1, 0, 0><<<dim3(32, 9, B_), 256>>>(
        wg, x, qkv, C_, C_, S_, S_,
        0, (size_t)C_ * S_, (size_t)OC3_ * S_,
        scl, b_qkv, nullptr, S_, 0);
    // 4) scores P[i][j] = (q^T k)/sqrt(C)   -> [b,4096,4096]
    gemm_kernel<0, 0, 1><<<dim3(32, 32, B_), 256>>>(
        qkv, qkv + (size_t)C_ * S_, P, C_, S_, S_, S_,
        (size_t)OC3_ * S_, (size_t)OC3_ * S_, (size_t)S_ * S_,
        nullptr, nullptr, nullptr, 0, 0);
    // 5) row softmax
    softmax_kernel<<<B_ * S_, 256>>>(P);
    // 6) O[c][i] = sum_j V[c][j] P[i][j]    -> [b,384,4096]
    gemm_kernel<1, 1, 2><<<dim3(32, 3, B_), 256>>>(
        qkv + (size_t)2 * C_ * S_, P, O, S_, S_, S_, S_,
        (size_t)OC3_ * S_, (size_t)S_ * S_, (size_t)C_ * S_,
        nullptr, nullptr, nullptr, 0, 0);
    // 7) out = Wp @ O + b_proj + x
    gemm_kernel<1, 0, 3><<<dim3(32, 3, B_), 256>>>(
        w_proj, O, out, C_, C_, S_, S_,
        0, (size_t)C_ * S_, (size_t)C_ * S_,
        nullptr, b_proj, x, 0, (size_t)C_ * S_);
}

// round 7
// speedup vs baseline: 3.0088x; 3.0088x over previous
#include <cuda_runtime.h>
#include <cstdint>
#include <cstddef>

// Problem constants
#define B_   4
#define C_   384
#define S_   4096

// ---------------------------------------------------------------------------
// Scratch (device globals; no allocation allowed in kernel_launch)
// ---------------------------------------------------------------------------
__device__ float g_scl[B_ * S_];                           // per-pixel rms scale
__device__ float g_wg [3 * C_ * C_];                       // w_qkv * gamma (tf32-rounded)
__device__ float g_xnt[(size_t)B_ * S_ * C_];              // [b][s][c] normed x
__device__ float g_qkt[(size_t)B_ * S_ * 2 * C_];          // [b][s][q|k]
__device__ float g_v  [(size_t)B_ * C_ * S_];              // [b][c][s]
__device__ float g_P  [(size_t)B_ * S_ * S_];              // [b][i][j]
__device__ float g_Ot [(size_t)B_ * S_ * C_];              // [b][s][c]

// ---------------------------------------------------------------------------
// PTX helpers (baseline ISA only — no sm_103a-suffixed features)
// ---------------------------------------------------------------------------
#define CP_ASYNC16(dst, src) \
    asm volatile("cp.async.cg.shared.global [%0], [%1], 16;" :: "r"(dst), "l"(src))
#define CP_COMMIT() asm volatile("cp.async.commit_group;" ::: "memory")
#define CP_WAIT(n)  asm volatile("cp.async.wait_group %0;" :: "n"(n) : "memory")

__device__ __forceinline__ void ldsm4(uint32_t& r0, uint32_t& r1, uint32_t& r2,
                                      uint32_t& r3, uint32_t addr) {
    asm volatile("ldmatrix.sync.aligned.m8n8.x4.shared.b16 {%0,%1,%2,%3}, [%4];"
                 : "=r"(r0), "=r"(r1), "=r"(r2), "=r"(r3) : "r"(addr));
}

__device__ __forceinline__ void mma8(float* c, const uint32_t* a, const uint32_t* b) {
    asm volatile(
        "mma.sync.aligned.m16n8k8.row.col.f32.tf32.tf32.f32 "
        "{%0,%1,%2,%3}, {%4,%5,%6,%7}, {%8,%9}, {%0,%1,%2,%3};"
        : "+f"(c[0]), "+f"(c[1]), "+f"(c[2]), "+f"(c[3])
        : "r"(a[0]), "r"(a[1]), "r"(a[2]), "r"(a[3]), "r"(b[0]), "r"(b[1]));
}

// round-to-nearest tf32 (kills the biased in-MMA truncation on later GEMMs)
__device__ __forceinline__ float tf32r(float x) {
    uint32_t u;
    asm("cvt.rna.tf32.f32 %0, %1;" : "=r"(u) : "f"(x));
    return __uint_as_float(u);
}

// ---------------------------------------------------------------------------
// Prep kernels
// ---------------------------------------------------------------------------
__global__ void wg_kernel(float* __restrict__ wg, const float* __restrict__ w,
                          const float* __restrict__ g) {
    int i = blockIdx.x * 256 + threadIdx.x;
    if (i < 3 * C_ * C_) wg[i] = tf32r(w[i] * g[i % C_]);
}

__global__ void scale_kernel(float* __restrict__ scl, const float* __restrict__ x) {
    int s = blockIdx.x * 256 + threadIdx.x;
    int b = blockIdx.y;
    const float* xb = x + (size_t)b * C_ * S_ + s;
    float acc = 0.f;
#pragma unroll 8
    for (int c = 0; c < C_; ++c) {
        float v = xb[(size_t)c * S_];
        acc += v * v;
    }
    float l2 = sqrtf(acc);
    scl[b * S_ + s] = 19.595917942265423f / fmaxf(l2, 1e-12f);  // sqrt(384)/max(l2,eps)
}

// transpose + scale: xnt[b][s][c] = round_tf32(x[b][c][s] * scl[b][s])
__global__ void xnt_kernel(float* __restrict__ xnt, const float* __restrict__ x,
                           const float* __restrict__ scl) {
    __shared__ float t[32][33];
    int b = blockIdx.z;
    int s0 = blockIdx.x * 32, c0 = blockIdx.y * 32;
    int tx = threadIdx.x, ty = threadIdx.y;   // 32 x 8
    const float* xb = x + (size_t)b * C_ * S_;
#pragma unroll
    for (int i = 0; i < 4; ++i)
        t[ty + i * 8][tx] = xb[(size_t)(c0 + ty + i * 8) * S_ + s0 + tx];
    __syncthreads();
    float* o = xnt + (size_t)b * S_ * C_;
#pragma unroll
    for (int i = 0; i < 4; ++i) {
        int s = s0 + ty + i * 8;
        o[(size_t)s * C_ + c0 + tx] = tf32r(t[tx][ty + i * 8] * scl[b * S_ + s]);
    }
}

// ---------------------------------------------------------------------------
// Warp-MMA tf32 GEMM: D[m][n] = sum_k A[m][k]*B[n][k]
// 128x128 block tile, 8 warps (4M x 2N, warp tile 32x64), Kc=16,
// 4-stage cp.async pipeline, ldmatrix operand fetch.
//   EPI 0: +e2[n], round      (qk bias)
//   EPI 1: +e2[m], round      (v bias)
//   EPI 2: *1/sqrt(C)         (scores; softmax rounds later)
//   EPI 3: plain, round       (AV -> Ot)
//   EPI 4: +e2[m] + e3[m*ldc+n]  (proj bias + residual; final, no round)
// All dims exact multiples of 128 (M,N) and 16 (K).
// ---------------------------------------------------------------------------
#define SROW 20                      // floats per smem row (16 + 4 pad)
#define STG_F (128 * SROW * 2)       // floats per pipeline stage (A+B) = 5120
#define NSTG 4

template <int EPI>
__global__ __launch_bounds__(256)
void mma_gemm(const float* __restrict__ Ag, const float* __restrict__ Bg,
              float* __restrict__ Cg, int K, int lda, int ldb, int ldc,
              size_t sA, size_t sB, size_t sC,
              const float* __restrict__ e2, const float* __restrict__ e3, size_t e3s)
{
    extern __shared__ __align__(16) float smem[];   // NSTG * STG_F floats

    const int tid  = threadIdx.x;
    const int lane = tid & 31, wid = tid >> 5;
    const int warpM = wid & 3, warpN = wid >> 2;
    const int bz = blockIdx.z;
    const int m0 = blockIdx.y * 128, n0 = blockIdx.x * 128;

    const float* A  = Ag + (size_t)bz * sA + (size_t)m0 * lda;
    const float* Bp = Bg + (size_t)bz * sB + (size_t)n0 * ldb;
    const uint32_t smB = (uint32_t)__cvta_generic_to_shared(smem);

    // global->smem loader mapping: thread covers rows lr and lr+64, 16B at k-offset lq
    const int lr = tid >> 2;
    const int lq = (tid & 3) * 4;

    // ldmatrix per-thread source addresses
    const int g = lane >> 3, r = lane & 7;
    const uint32_t aOff = (uint32_t)(((warpM * 32 + (g & 1) * 8 + r) * SROW + (g >> 1) * 4) * 4);
    const uint32_t bOff = (uint32_t)((128 * SROW + (warpN * 64 + (g >> 1) * 8 + r) * SROW + (g & 1) * 4) * 4);

    float acc[2][8][4];
#pragma unroll
    for (int mf = 0; mf < 2; ++mf)
#pragma unroll
        for (int nf = 0; nf < 8; ++nf)
#pragma unroll
            for (int i = 0; i < 4; ++i) acc[mf][nf][i] = 0.f;

    const int nK = K >> 4;

    auto LOAD = [&](int s) {
        const int p = s & (NSTG - 1);
        const float* As = A + s * 16 + lq;
        const float* Bs = Bp + s * 16 + lq;
        uint32_t dA = smB + (uint32_t)((p * STG_F + lr * SROW + lq) * 4);
        uint32_t dB = dA + (uint32_t)(128 * SROW * 4);
        CP_ASYNC16(dA,                         As + (size_t)lr * lda);
        CP_ASYNC16(dA + 64 * SROW * 4,         As + (size_t)(lr + 64) * lda);
        CP_ASYNC16(dB,                         Bs + (size_t)lr * ldb);
        CP_ASYNC16(dB + 64 * SROW * 4,         Bs + (size_t)(lr + 64) * ldb);
    };

    LOAD(0); CP_COMMIT();
    LOAD(1); CP_COMMIT();
    LOAD(2); CP_COMMIT();

    for (int s = 0; s < nK; ++s) {
        CP_WAIT(2);              // stage s landed
        __syncthreads();         // visible to all; also fences buffer reuse
        if (s + 3 < nK) LOAD(s + 3);
        CP_COMMIT();             // empty group near tail keeps counts uniform

        const uint32_t pb = smB + (uint32_t)((s & (NSTG - 1)) * STG_F * 4);
#pragma unroll
        for (int kk = 0; kk < 2; ++kk) {
            uint32_t afr[2][4], bfr[8][2];
#pragma unroll
            for (int mf = 0; mf < 2; ++mf)
                ldsm4(afr[mf][0], afr[mf][1], afr[mf][2], afr[mf][3],
                      pb + aOff + (uint32_t)(mf * 16 * SROW * 4 + kk * 32));
#pragma unroll
            for (int pr = 0; pr < 4; ++pr)
                ldsm4(bfr[2 * pr][0], bfr[2 * pr][1], bfr[2 * pr + 1][0], bfr[2 * pr + 1][1],
                      pb + bOff + (uint32_t)(pr * 16 * SROW * 4 + kk * 32));
#pragma unroll
            for (int mf = 0; mf < 2; ++mf)
#pragma unroll
                for (int nf = 0; nf < 8; ++nf)
                    mma8(acc[mf][nf], afr[mf], bfr[nf]);
        }
    }

    // ---- epilogue ----
    float* Cp = Cg + (size_t)bz * sC;
    const int rBase = m0 + warpM * 32 + (lane >> 2);
    const int cBase = n0 + warpN * 64 + (lane & 3) * 2;
#pragma unroll
    for (int mf = 0; mf < 2; ++mf) {
#pragma unroll
        for (int h = 0; h < 2; ++h) {
            const int row = rBase + mf * 16 + h * 8;
            float bm = 0.f;
            if (EPI == 1 || EPI == 4) bm = e2[row];
            float* Crow = Cp + (size_t)row * ldc;
            const float* e3row =
                (EPI == 4) ? (e3 + (size_t)bz * e3s + (size_t)row * ldc) : nullptr;
#pragma unroll
            for (int nf = 0; nf < 8; ++nf) {
                const int col = cBase + nf * 8;
                float u0 = acc[mf][nf][2 * h];
                float u1 = acc[mf][nf][2 * h + 1];
                float2 o;
                if (EPI == 0) {
                    float2 bn = *(const float2*)(e2 + col);
                    o.x = tf32r(u0 + bn.x); o.y = tf32r(u1 + bn.y);
                } else if (EPI == 1) {
                    o.x = tf32r(u0 + bm); o.y = tf32r(u1 + bm);
                } else if (EPI == 2) {
                    const float sc = 0.05103103630798288f;   // 1/sqrt(384)
                    o.x = u0 * sc; o.y = u1 * sc;
                } else if (EPI == 3) {
                    o.x = tf32r(u0); o.y = tf32r(u1);
                } else {
                    float2 rx = *(const float2*)(e3row + col);
                    o.x = u0 + bm + rx.x; o.y = u1 + bm + rx.y;
                }
                *(float2*)(Crow + col) = o;
            }
        }
    }
}

// ---------------------------------------------------------------------------
// Row softmax over 4096 columns, one block per row (tf32-rounded output).
// ---------------------------------------------------------------------------
__global__ void softmax_kernel(float* __restrict__ P) {
    float4* p = reinterpret_cast<float4*>(P + (size_t)blockIdx.x * S_);
    const int t = threadIdx.x;

    float4 v[4];
    float mx = -3.4e38f;
#pragma unroll
    for (int i = 0; i < 4; ++i) {
        v[i] = p[t + i * 256];
        mx = fmaxf(mx, fmaxf(fmaxf(v[i].x, v[i].y), fmaxf(v[i].z, v[i].w)));
    }
    __shared__ float redMax[8];
    __shared__ float redSum[8];
#pragma unroll
    for (int o = 16; o > 0; o >>= 1)
        mx = fmaxf(mx, __shfl_xor_sync(0xffffffffu, mx, o));
    if ((t & 31) == 0) redMax[t >> 5] = mx;
    __syncthreads();
    mx = redMax[0];
#pragma unroll
    for (int w = 1; w < 8; ++w) mx = fmaxf(mx, redMax[w]);

    float sum = 0.f;
#pragma unroll
    for (int i = 0; i < 4; ++i) {
        v[i].x = __expf(v[i].x - mx);
        v[i].y = __expf(v[i].y - mx);
        v[i].z = __expf(v[i].z - mx);
        v[i].w = __expf(v[i].w - mx);
        sum += (v[i].x + v[i].y) + (v[i].z + v[i].w);
    }
#pragma unroll
    for (int o = 16; o > 0; o >>= 1)
        sum += __shfl_xor_sync(0xffffffffu, sum, o);
    if ((t & 31) == 0) redSum[t >> 5] = sum;
    __syncthreads();
    sum = (redSum[0] + redSum[1]) + (redSum[2] + redSum[3]) +
          (redSum[4] + redSum[5]) + (redSum[6] + redSum[7]);
    float inv = 1.f / sum;
#pragma unroll
    for (int i = 0; i < 4; ++i) {
        v[i].x = tf32r(v[i].x * inv); v[i].y = tf32r(v[i].y * inv);
        v[i].z = tf32r(v[i].z * inv); v[i].w = tf32r(v[i].w * inv);
        p[t + i * 256] = v[i];
    }
}

// ---------------------------------------------------------------------------
// Launch
// ---------------------------------------------------------------------------
extern "C" void kernel_launch(void* const* d_in, const int* in_sizes, int n_in,
                              void* d_out, int out_size) {
    const float* x      = (const float*)d_in[0];   // [4,384,64,64]
    const float* gamma  = (const float*)d_in[1];   // [384]
    const float* w_qkv  = (const float*)d_in[2];   // [1152,384]
    const float* b_qkv  = (const float*)d_in[3];   // [1152]
    const float* w_proj = (const float*)d_in[4];   // [384,384]
    const float* b_proj = (const float*)d_in[5];   // [384]
    float* out = (float*)d_out;                    // [4,384,64,64]

    float *scl, *wg, *xnt, *qkt, *v, *P, *Ot;
    cudaGetSymbolAddress((void**)&scl, g_scl);
    cudaGetSymbolAddress((void**)&wg,  g_wg);
    cudaGetSymbolAddress((void**)&xnt, g_xnt);
    cudaGetSymbolAddress((void**)&qkt, g_qkt);
    cudaGetSymbolAddress((void**)&v,   g_v);
    cudaGetSymbolAddress((void**)&P,   g_P);
    cudaGetSymbolAddress((void**)&Ot,  g_Ot);

    const int SMEM_DYN = NSTG * STG_F * 4;   // 81920 bytes
    cudaFuncSetAttribute(mma_gemm<0>, cudaFuncAttributeMaxDynamicSharedMemorySize, SMEM_DYN);
    cudaFuncSetAttribute(mma_gemm<1>, cudaFuncAttributeMaxDynamicSharedMemorySize, SMEM_DYN);
    cudaFuncSetAttribute(mma_gemm<2>, cudaFuncAttributeMaxDynamicSharedMemorySize, SMEM_DYN);
    cudaFuncSetAttribute(mma_gemm<3>, cudaFuncAttributeMaxDynamicSharedMemorySize, SMEM_DYN);
    cudaFuncSetAttribute(mma_gemm<4>, cudaFuncAttributeMaxDynamicSharedMemorySize, SMEM_DYN);

    // 1) fold gamma into w_qkv (tf32-rounded)
    wg_kernel<<<(3 * C_ * C_ + 255) / 256, 256>>>(wg, w_qkv, gamma);
    // 2) per-pixel rms scale
    scale_kernel<<<dim3(S_ / 256, B_), 256>>>(scl, x);
    // 3) xnt[b][s][c] = x[b][c][s] * scl (tf32-rounded)
    xnt_kernel<<<dim3(S_ / 32, C_ / 32, B_), dim3(32, 8)>>>(xnt, x, scl);
    // 4) qk_t[b][s][o] = xnt @ wg[0:768]^T + b_qkv[o]      M=4096 N=768 K=384
    mma_gemm<0><<<dim3(6, 32, B_), 256, SMEM_DYN>>>(
        xnt, wg, qkt, C_, C_, C_, 2 * C_,
        (size_t)S_ * C_, 0, (size_t)S_ * 2 * C_, b_qkv, nullptr, 0);
    // 5) v[b][c][s] = wg[768:] @ xnt^T + b_qkv[768+c]      M=384 N=4096 K=384
    mma_gemm<1><<<dim3(32, 3, B_), 256, SMEM_DYN>>>(
        wg + (size_t)2 * C_ * C_, xnt, v, C_, C_, C_, S_,
        0, (size_t)S_ * C_, (size_t)C_ * S_, b_qkv + 2 * C_, nullptr, 0);
    // 6) P[b][i][j] = q_i . k_j / sqrt(C)                  M=N=4096 K=384
    mma_gemm<2><<<dim3(32, 32, B_), 256, SMEM_DYN>>>(
        qkt, qkt + C_, P, C_, 2 * C_, 2 * C_, S_,
        (size_t)S_ * 2 * C_, (size_t)S_ * 2 * C_, (size_t)S_ * S_, nullptr, nullptr, 0);
    // 7) softmax rows
    softmax_kernel<<<B_ * S_, 256>>>(P);
    // 8) Ot[b][i][c] = P @ v^T                             M=4096 N=384 K=4096
    mma_gemm<3><<<dim3(3, 32, B_), 256, SMEM_DYN>>>(
        P, v, Ot, S_, S_, S_, C_,
        (size_t)S_ * S_, (size_t)C_ * S_, (size_t)S_ * C_, nullptr, nullptr, 0);
    // 9) out[b][o][s] = Wp @ Ot^T + b_proj[o] + x          M=384 N=4096 K=384
    mma_gemm<4><<<dim3(32, 3, B_), 256, SMEM_DYN>>>(
        w_proj, Ot, out, C_, C_, C_, S_,
        0, (size_t)S_ * C_, (size_t)C_ * S_, b_proj, x, (size_t)C_ * S_);
}

// round 8
// speedup vs baseline: 4.9964x; 1.6606x over previous
#include <cuda_runtime.h>
#include <cuda_bf16.h>
#include <cstdint>
#include <cstddef>

// Problem constants
#define B_   4
#define C_   384
#define S_   4096

typedef __nv_bfloat16 bf16;

// ---------------------------------------------------------------------------
// Scratch (device globals; no allocation allowed in kernel_launch)
// ---------------------------------------------------------------------------
__device__ float g_scl[B_ * S_];                          // per-pixel rms scale
__device__ bf16  g_wg [3 * C_ * C_];                      // bf16(w_qkv * gamma)
__device__ bf16  g_wp [C_ * C_];                          // bf16(w_proj)
__device__ bf16  g_xnt[(size_t)B_ * S_ * C_];             // [b][s][c] normed x
__device__ bf16  g_qkt[(size_t)B_ * S_ * 2 * C_];         // [b][s][q|k]
__device__ bf16  g_v  [(size_t)B_ * C_ * S_];             // [b][c][s]
__device__ bf16  g_P  [(size_t)B_ * S_ * S_];             // [b][i][j]
__device__ bf16  g_Ot [(size_t)B_ * S_ * C_];             // [b][s][c]

// ---------------------------------------------------------------------------
// PTX helpers (baseline ISA only)
// ---------------------------------------------------------------------------
#define CP_ASYNC16(dst, src) \
    asm volatile("cp.async.cg.shared.global [%0], [%1], 16;" :: "r"(dst), "l"(src))
#define CP_COMMIT() asm volatile("cp.async.commit_group;" ::: "memory")
#define CP_WAIT(n)  asm volatile("cp.async.wait_group %0;" :: "n"(n) : "memory")

__device__ __forceinline__ void ldsm4(uint32_t& r0, uint32_t& r1, uint32_t& r2,
                                      uint32_t& r3, uint32_t addr) {
    asm volatile("ldmatrix.sync.aligned.m8n8.x4.shared.b16 {%0,%1,%2,%3}, [%4];"
                 : "=r"(r0), "=r"(r1), "=r"(r2), "=r"(r3) : "r"(addr));
}

__device__ __forceinline__ void mma16(float* c, const uint32_t* a, const uint32_t* b) {
    asm volatile(
        "mma.sync.aligned.m16n8k16.row.col.f32.bf16.bf16.f32 "
        "{%0,%1,%2,%3}, {%4,%5,%6,%7}, {%8,%9}, {%0,%1,%2,%3};"
        : "+f"(c[0]), "+f"(c[1]), "+f"(c[2]), "+f"(c[3])
        : "r"(a[0]), "r"(a[1]), "r"(a[2]), "r"(a[3]), "r"(b[0]), "r"(b[1]));
}

// ---------------------------------------------------------------------------
// Prep kernels
// ---------------------------------------------------------------------------
__global__ void wg_kernel(bf16* __restrict__ wg, const float* __restrict__ w,
                          const float* __restrict__ g) {
    int i = blockIdx.x * 256 + threadIdx.x;
    if (i < 3 * C_ * C_) wg[i] = __float2bfloat16_rn(w[i] * g[i % C_]);
}

__global__ void wp_kernel(bf16* __restrict__ wp, const float* __restrict__ w) {
    int i = blockIdx.x * 256 + threadIdx.x;
    if (i < C_ * C_) wp[i] = __float2bfloat16_rn(w[i]);
}

__global__ void scale_kernel(float* __restrict__ scl, const float* __restrict__ x) {
    int s = blockIdx.x * 256 + threadIdx.x;
    int b = blockIdx.y;
    const float* xb = x + (size_t)b * C_ * S_ + s;
    float acc = 0.f;
#pragma unroll 8
    for (int c = 0; c < C_; ++c) {
        float v = xb[(size_t)c * S_];
        acc += v * v;
    }
    float l2 = sqrtf(acc);
    scl[b * S_ + s] = 19.595917942265423f / fmaxf(l2, 1e-12f);  // sqrt(384)/max(l2,eps)
}

// transpose + scale: xnt[b][s][c] = bf16(x[b][c][s] * scl[b][s])
__global__ void xnt_kernel(bf16* __restrict__ xnt, const float* __restrict__ x,
                           const float* __restrict__ scl) {
    __shared__ float t[32][33];
    int b = blockIdx.z;
    int s0 = blockIdx.x * 32, c0 = blockIdx.y * 32;
    int tx = threadIdx.x, ty = threadIdx.y;   // 32 x 8
    const float* xb = x + (size_t)b * C_ * S_;
#pragma unroll
    for (int i = 0; i < 4; ++i)
        t[ty + i * 8][tx] = xb[(size_t)(c0 + ty + i * 8) * S_ + s0 + tx];
    __syncthreads();
    bf16* o = xnt + (size_t)b * S_ * C_;
#pragma unroll
    for (int i = 0; i < 4; ++i) {
        int s = s0 + ty + i * 8;
        o[(size_t)s * C_ + c0 + tx] =
            __float2bfloat16_rn(t[tx][ty + i * 8] * scl[b * S_ + s]);
    }
}

// ---------------------------------------------------------------------------
// Warp-MMA bf16 GEMM: D[m][n] = sum_k A[m][k]*B[n][k]
// 128x128 block tile, 8 warps (4M x 2N, warp tile 32x64), Kc=32 (2 k16 steps),
// 4-stage cp.async pipeline, ldmatrix operand fetch, fp32 accumulate.
//   EPI 0: +e2[n]  -> bf16   (qk bias)
//   EPI 1: +e2[m]  -> bf16   (v bias)
//   EPI 2: *1/sqrt(C) -> bf16 (scores)
//   EPI 3: plain   -> bf16   (AV -> Ot)
//   EPI 4: +e2[m] + e3[m*ldc+n] -> fp32 (proj bias + residual)
// All M,N multiples of 128; K multiple of 32.
// ---------------------------------------------------------------------------
#define SRB    80                    // bytes per smem row (64 data + 16 pad)
#define ATILEB (128 * SRB)           // 10240 B per operand tile
#define STGB   (2 * ATILEB)          // 20480 B per stage
#define NSTG   4

template <int EPI>
__global__ __launch_bounds__(256)
void mma_gemm(const bf16* __restrict__ Ag, const bf16* __restrict__ Bg,
              void* __restrict__ Cgv, int K, int lda, int ldb, int ldc,
              size_t sA, size_t sB, size_t sC,
              const float* __restrict__ e2, const float* __restrict__ e3, size_t e3s)
{
    extern __shared__ __align__(16) char smem[];   // NSTG * STGB bytes

    const int tid  = threadIdx.x;
    const int lane = tid & 31, wid = tid >> 5;
    const int warpM = wid & 3, warpN = wid >> 2;
    const int bz = blockIdx.z;
    const int m0 = blockIdx.y * 128, n0 = blockIdx.x * 128;

    const bf16* A  = Ag + (size_t)bz * sA + (size_t)m0 * lda;
    const bf16* Bp = Bg + (size_t)bz * sB + (size_t)n0 * ldb;
    const uint32_t smB = (uint32_t)__cvta_generic_to_shared(smem);

    // global->smem loader mapping: thread covers rows lr and lr+64, 16B at k-halfs lq
    const int lr = tid >> 2;
    const int lq = (tid & 3) * 8;              // halfs
    const uint32_t lqB = (uint32_t)(tid & 3) * 16;  // bytes

    // ldmatrix per-thread source offsets (bytes within a stage)
    const int g = lane >> 3, r = lane & 7;
    const uint32_t aOff = (uint32_t)((warpM * 32 + (g & 1) * 8 + r) * SRB + (g >> 1) * 16);
    const uint32_t bOff = (uint32_t)(ATILEB + (warpN * 64 + (g & 1) * 8 + r) * SRB + (g >> 1) * 16);

    float acc[2][8][4];
#pragma unroll
    for (int mf = 0; mf < 2; ++mf)
#pragma unroll
        for (int nf = 0; nf < 8; ++nf)
#pragma unroll
            for (int i = 0; i < 4; ++i) acc[mf][nf][i] = 0.f;

    const int nK = K >> 5;   // Kc = 32

    auto LOAD = [&](int s) {
        const int p = s & (NSTG - 1);
        const bf16* As = A  + (size_t)lr * lda + s * 32 + lq;
        const bf16* Bs = Bp + (size_t)lr * ldb + s * 32 + lq;
        uint32_t dA = smB + (uint32_t)(p * STGB + lr * SRB) + lqB;
        uint32_t dB = dA + (uint32_t)ATILEB;
        CP_ASYNC16(dA,                As);
        CP_ASYNC16(dA + 64 * SRB,     As + (size_t)64 * lda);
        CP_ASYNC16(dB,                Bs);
        CP_ASYNC16(dB + 64 * SRB,     Bs + (size_t)64 * ldb);
    };

    LOAD(0); CP_COMMIT();
    LOAD(1); CP_COMMIT();
    LOAD(2); CP_COMMIT();

    for (int s = 0; s < nK; ++s) {
        CP_WAIT(2);              // stage s landed
        __syncthreads();         // visibility + buffer-reuse fence
        if (s + 3 < nK) LOAD(s + 3);
        CP_COMMIT();             // empty group at tail keeps counts uniform

        const uint32_t pb = smB + (uint32_t)((s & (NSTG - 1)) * STGB);
#pragma unroll
        for (int kk = 0; kk < 2; ++kk) {      // two k16 steps per stage
            uint32_t afr[2][4], bfr[8][2];
#pragma unroll
            for (int mf = 0; mf < 2; ++mf)
                ldsm4(afr[mf][0], afr[mf][1], afr[mf][2], afr[mf][3],
                      pb + aOff + (uint32_t)(mf * 16 * SRB + kk * 32));
#pragma unroll
            for (int pr = 0; pr < 4; ++pr)
                ldsm4(bfr[2 * pr][0], bfr[2 * pr + 1][0],
                      bfr[2 * pr][1], bfr[2 * pr + 1][1],
                      pb + bOff + (uint32_t)(pr * 16 * SRB + kk * 32));
#pragma unroll
            for (int mf = 0; mf < 2; ++mf)
#pragma unroll
                for (int nf = 0; nf < 8; ++nf)
                    mma16(acc[mf][nf], afr[mf], bfr[nf]);
        }
    }

    // ---- epilogue ----
    const int rBase = m0 + warpM * 32 + (lane >> 2);
    const int cBase = n0 + warpN * 64 + (lane & 3) * 2;
#pragma unroll
    for (int mf = 0; mf < 2; ++mf) {
#pragma unroll
        for (int h = 0; h < 2; ++h) {
            const int row = rBase + mf * 16 + h * 8;
            float bm = 0.f;
            if (EPI == 1 || EPI == 4) bm = e2[row];
#pragma unroll
            for (int nf = 0; nf < 8; ++nf) {
                const int col = cBase + nf * 8;
                float u0 = acc[mf][nf][2 * h];
                float u1 = acc[mf][nf][2 * h + 1];
                float2 o;
                if (EPI == 0) {
                    float2 bn = *(const float2*)(e2 + col);
                    o.x = u0 + bn.x; o.y = u1 + bn.y;
                } else if (EPI == 1) {
                    o.x = u0 + bm; o.y = u1 + bm;
                } else if (EPI == 2) {
                    const float sc = 0.05103103630798288f;   // 1/sqrt(384)
                    o.x = u0 * sc; o.y = u1 * sc;
                } else if (EPI == 3) {
                    o.x = u0; o.y = u1;
                } else {
                    const float* e3row = e3 + (size_t)bz * e3s + (size_t)row * ldc;
                    float2 rx = *(const float2*)(e3row + col);
                    o.x = u0 + bm + rx.x; o.y = u1 + bm + rx.y;
                }
                if (EPI == 4) {
                    float* Crow = (float*)Cgv + (size_t)bz * sC + (size_t)row * ldc;
                    *(float2*)(Crow + col) = o;
                } else {
                    bf16* Crow = (bf16*)Cgv + (size_t)bz * sC + (size_t)row * ldc;
                    __nv_bfloat162 hv = __floats2bfloat162_rn(o.x, o.y);
                    *(__nv_bfloat162*)(Crow + col) = hv;
                }
            }
        }
    }
}

// ---------------------------------------------------------------------------
// Row softmax over 4096 bf16 columns, one block (256 thr) per row.
// ---------------------------------------------------------------------------
__global__ void softmax_kernel(bf16* __restrict__ P) {
    uint4* p = reinterpret_cast<uint4*>(P + (size_t)blockIdx.x * S_);
    const int t = threadIdx.x;

    uint4 u[2] = { p[t], p[t + 256] };
    float f[16];
#pragma unroll
    for (int i = 0; i < 2; ++i) {
        const uint32_t* w = (const uint32_t*)&u[i];
#pragma unroll
        for (int j = 0; j < 4; ++j) {
            float2 d = __bfloat1622float2(*(const __nv_bfloat162*)&w[j]);
            f[i * 8 + 2 * j] = d.x;
            f[i * 8 + 2 * j + 1] = d.y;
        }
    }

    float mx = -3.4e38f;
#pragma unroll
    for (int i = 0; i < 16; ++i) mx = fmaxf(mx, f[i]);

    __shared__ float redMax[8];
    __shared__ float redSum[8];
#pragma unroll
    for (int o = 16; o > 0; o >>= 1)
        mx = fmaxf(mx, __shfl_xor_sync(0xffffffffu, mx, o));
    if ((t & 31) == 0) redMax[t >> 5] = mx;
    __syncthreads();
    mx = redMax[0];
#pragma unroll
    for (int w = 1; w < 8; ++w) mx = fmaxf(mx, redMax[w]);

    float sum = 0.f;
#pragma unroll
    for (int i = 0; i < 16; ++i) {
        f[i] = __expf(f[i] - mx);
        sum += f[i];
    }
#pragma unroll
    for (int o = 16; o > 0; o >>= 1)
        sum += __shfl_xor_sync(0xffffffffu, sum, o);
    if ((t & 31) == 0) redSum[t >> 5] = sum;
    __syncthreads();
    sum = (redSum[0] + redSum[1]) + (redSum[2] + redSum[3]) +
          (redSum[4] + redSum[5]) + (redSum[6] + redSum[7]);
    float inv = 1.f / sum;

#pragma unroll
    for (int i = 0; i < 2; ++i) {
        uint32_t* w = (uint32_t*)&u[i];
#pragma unroll
        for (int j = 0; j < 4; ++j) {
            __nv_bfloat162 hv = __floats2bfloat162_rn(f[i * 8 + 2 * j] * inv,
                                                      f[i * 8 + 2 * j + 1] * inv);
            w[j] = *(const uint32_t*)&hv;
        }
    }
    p[t] = u[0];
    p[t + 256] = u[1];
}

// ---------------------------------------------------------------------------
// Launch
// ---------------------------------------------------------------------------
extern "C" void kernel_launch(void* const* d_in, const int* in_sizes, int n_in,
                              void* d_out, int out_size) {
    const float* x      = (const float*)d_in[0];   // [4,384,64,64]
    const float* gamma  = (const float*)d_in[1];   // [384]
    const float* w_qkv  = (const float*)d_in[2];   // [1152,384]
    const float* b_qkv  = (const float*)d_in[3];   // [1152]
    const float* w_proj = (const float*)d_in[4];   // [384,384]
    const float* b_proj = (const float*)d_in[5];   // [384]
    float* out = (float*)d_out;                    // [4,384,64,64]

    float *scl;
    bf16 *wg, *wp, *xnt, *qkt, *v, *P, *Ot;
    cudaGetSymbolAddress((void**)&scl, g_scl);
    cudaGetSymbolAddress((void**)&wg,  g_wg);
    cudaGetSymbolAddress((void**)&wp,  g_wp);
    cudaGetSymbolAddress((void**)&xnt, g_xnt);
    cudaGetSymbolAddress((void**)&qkt, g_qkt);
    cudaGetSymbolAddress((void**)&v,   g_v);
    cudaGetSymbolAddress((void**)&P,   g_P);
    cudaGetSymbolAddress((void**)&Ot,  g_Ot);

    const int SMEM_DYN = NSTG * STGB;   // 81920 bytes
    cudaFuncSetAttribute(mma_gemm<0>, cudaFuncAttributeMaxDynamicSharedMemorySize, SMEM_DYN);
    cudaFuncSetAttribute(mma_gemm<1>, cudaFuncAttributeMaxDynamicSharedMemorySize, SMEM_DYN);
    cudaFuncSetAttribute(mma_gemm<2>, cudaFuncAttributeMaxDynamicSharedMemorySize, SMEM_DYN);
    cudaFuncSetAttribute(mma_gemm<3>, cudaFuncAttributeMaxDynamicSharedMemorySize, SMEM_DYN);
    cudaFuncSetAttribute(mma_gemm<4>, cudaFuncAttributeMaxDynamicSharedMemorySize, SMEM_DYN);

    // 1) fold gamma into w_qkv (bf16); convert w_proj (bf16)
    wg_kernel<<<(3 * C_ * C_ + 255) / 256, 256>>>(wg, w_qkv, gamma);
    wp_kernel<<<(C_ * C_ + 255) / 256, 256>>>(wp, w_proj);
    // 2) per-pixel rms scale
    scale_kernel<<<dim3(S_ / 256, B_), 256>>>(scl, x);
    // 3) xnt[b][s][c] = bf16(x[b][c][s] * scl)
    xnt_kernel<<<dim3(S_ / 32, C_ / 32, B_), dim3(32, 8)>>>(xnt, x, scl);
    // 4) qk_t[b][s][o] = xnt @ wg[0:768]^T + b_qkv[o]      M=4096 N=768 K=384
    mma_gemm<0><<<dim3(6, 32, B_), 256, SMEM_DYN>>>(
        xnt, wg, qkt, C_, C_, C_, 2 * C_,
        (size_t)S_ * C_, 0, (size_t)S_ * 2 * C_, b_qkv, nullptr, 0);
    // 5) v[b][c][s] = wg[768:] @ xnt^T + b_qkv[768+c]      M=384 N=4096 K=384
    mma_gemm<1><<<dim3(32, 3, B_), 256, SMEM_DYN>>>(
        wg + (size_t)2 * C_ * C_, xnt, v, C_, C_, C_, S_,
        0, (size_t)S_ * C_, (size_t)C_ * S_, b_qkv + 2 * C_, nullptr, 0);
    // 6) P[b][i][j] = q_i . k_j / sqrt(C)                  M=N=4096 K=384
    mma_gemm<2><<<dim3(32, 32, B_), 256, SMEM_DYN>>>(
        qkt, qkt + C_, P, C_, 2 * C_, 2 * C_, S_,
        (size_t)S_ * 2 * C_, (size_t)S_ * 2 * C_, (size_t)S_ * S_, nullptr, nullptr, 0);
    // 7) softmax rows
    softmax_kernel<<<B_ * S_, 256>>>(P);
    // 8) Ot[b][i][c] = P @ v^T                             M=4096 N=384 K=4096
    mma_gemm<3><<<dim3(3, 32, B_), 256, SMEM_DYN>>>(
        P, v, Ot, S_, S_, S_, C_,
        (size_t)S_ * S_, (size_t)C_ * S_, (size_t)S_ * C_, nullptr, nullptr, 0);
    // 9) out[b][o][s] = Wp @ Ot^T + b_proj[o] + x          M=384 N=4096 K=384
    mma_gemm<4><<<dim3(32, 3, B_), 256, SMEM_DYN>>>(
        wp, Ot, out, C_, C_, C_, S_,
        0, (size_t)S_ * C_, (size_t)C_ * S_, b_proj, x, (size_t)C_ * S_);
}